// round 9
// baseline (speedup 1.0000x reference)
#include <cuda_runtime.h>
#include <cuda_bf16.h>
#include <cuda_fp16.h>

// ---------------------------------------------------------------------------
// UFF energy -> out[8]. Coords batch-PAIR-interleaved fp16:
//   g_c[atom*4 + bp] = { x(b0,b1), y(b0,b1), z(b0,b1), pad } (uint4, 16B)
// where b0 = 2*bp, b1 = 2*bp+1. 4 lanes x 2 batches per term; one LDG.128
// per atom per thread. All vector math (diff, dot, cross, norms) runs in
// half2 SIMD over the 2 batches; fp32 only for the scalar tail.
// ---------------------------------------------------------------------------

#define NBATCH 8
#define MAX_ATOMS 50000

__device__ uint4 g_c[MAX_ATOMS * 4];

__device__ __forceinline__ __half2 h2(unsigned u) {
    return *reinterpret_cast<__half2*>(&u);
}

__device__ __forceinline__ float clip1(float x) {
    return fminf(fmaxf(x, -0.999999f), 0.999999f);
}

// a*b - c*d  (cross-product component, both batches)
__device__ __forceinline__ __half2 cr(__half2 a, __half2 b, __half2 c, __half2 d) {
    return __hfma2(a, b, __hneg2(__hmul2(c, d)));
}

// 3-dot, both batches
__device__ __forceinline__ __half2 dot3(__half2 ax, __half2 ay, __half2 az,
                                        __half2 bx, __half2 by, __half2 bz) {
    return __hfma2(ax, bx, __hfma2(ay, by, __hmul2(az, bz)));
}

struct V3h { __half2 x, y, z; };

__device__ __forceinline__ V3h vdiff(uint4 a, uint4 c) {
    V3h r;
    r.x = __hsub2(h2(a.x), h2(c.x));
    r.y = __hsub2(h2(a.y), h2(c.y));
    r.z = __hsub2(h2(a.z), h2(c.z));
    return r;
}

__device__ __forceinline__ uint4 ldco(int atom, int bp) {
    return __ldg(&g_c[atom * 4 + bp]);
}

// ---------------------------------------------------------------------------
// pack: coords (B,N,3) f32 -> g_c; zero out[8]
// ---------------------------------------------------------------------------
__global__ void pack_kernel(const float* __restrict__ coords,
                            float* __restrict__ out, int natoms) {
    int i = blockIdx.x * blockDim.x + threadIdx.x;
    if (i < NBATCH) out[i] = 0.0f;
    if (i < natoms * 4) {
        int atom = i >> 2;
        int bp   = i & 3;
        size_t s0 = ((size_t)(2 * bp)     * natoms + atom) * 3;
        size_t s1 = ((size_t)(2 * bp + 1) * natoms + atom) * 3;
        __half2 x2 = __floats2half2_rn(__ldg(&coords[s0]),     __ldg(&coords[s1]));
        __half2 y2 = __floats2half2_rn(__ldg(&coords[s0 + 1]), __ldg(&coords[s1 + 1]));
        __half2 z2 = __floats2half2_rn(__ldg(&coords[s0 + 2]), __ldg(&coords[s1 + 2]));
        uint4 u;
        u.x = *reinterpret_cast<unsigned*>(&x2);
        u.y = *reinterpret_cast<unsigned*>(&y2);
        u.z = *reinterpret_cast<unsigned*>(&z2);
        u.w = 0;
        g_c[i] = u;
    }
}

// ---------------------------------------------------------------------------
// reduction: thread holds e0 (batch 2bp) and e1 (batch 2bp+1), bp = lane&3
// ---------------------------------------------------------------------------
__device__ __forceinline__ void reduce_out2(float e0, float e1,
                                            float* __restrict__ out) {
    #pragma unroll
    for (int off = 16; off >= 4; off >>= 1) {
        e0 += __shfl_down_sync(0xFFFFFFFFu, e0, off);
        e1 += __shfl_down_sync(0xFFFFFFFFu, e1, off);
    }
    __shared__ float s[NBATCH];
    if (threadIdx.x < NBATCH) s[threadIdx.x] = 0.0f;
    __syncthreads();
    if ((threadIdx.x & 31) < 4) {
        int bp = threadIdx.x & 3;
        atomicAdd(&s[2 * bp],     e0);
        atomicAdd(&s[2 * bp + 1], e1);
    }
    __syncthreads();
    if (threadIdx.x < NBATCH) atomicAdd(&out[threadIdx.x], s[threadIdx.x]);
}

// ---------------------------------------------------------------------------
// vdW helpers
// ---------------------------------------------------------------------------
__device__ __forceinline__ float d2_fp32(const float* __restrict__ coords,
                                         int natoms, int b, int2 p) {
    size_t sa = ((size_t)b * natoms + p.x) * 3;
    size_t sc = ((size_t)b * natoms + p.y) * 3;
    float dx = __ldg(&coords[sa])     - __ldg(&coords[sc]);
    float dy = __ldg(&coords[sa + 1]) - __ldg(&coords[sc + 1]);
    float dz = __ldg(&coords[sa + 2]) - __ldg(&coords[sc + 2]);
    return fmaf(dx, dx, fmaf(dy, dy, dz * dz));
}

__device__ __forceinline__ float lj(float d2, float R2, float D, float t2) {
    float x2 = R2 * __fdividef(1.0f, fmaxf(d2, 1e-12f));
    float x6 = x2 * x2 * x2;
    float ep = D * fmaf(x6, x6, -2.0f * x6);
    return (d2 <= t2) ? ep : 0.0f;
}

__device__ __forceinline__ void vdw_body(
    int t, int bp, const int2* __restrict__ cidx, const float* __restrict__ cR,
    const float* __restrict__ cD, const float* __restrict__ cT,
    const float* __restrict__ coords, int natoms, float& e0, float& e1)
{
    int2  p  = __ldg(&cidx[t]);
    float R  = __ldg(&cR[t]);
    float D  = __ldg(&cD[t]);
    float t2 = __ldg(&cT[t]);
    V3h d = vdiff(ldco(p.x, bp), ldco(p.y, bp));
    __half2 d2h = dot3(d.x, d.y, d.z, d.x, d.y, d.z);
    float2 d2 = __half22float2(d2h);
    if (fminf(d2.x, d2.y) < 4.0f) {
        // rare near-collision: (R/r)^12 is fp16-sensitive; redo in fp32
        if (d2.x < 4.0f) d2.x = d2_fp32(coords, natoms, 2 * bp,     p);
        if (d2.y < 4.0f) d2.y = d2_fp32(coords, natoms, 2 * bp + 1, p);
    }
    float R2 = R * R;
    e0 += lj(d2.x, R2, D, t2);
    e1 += lj(d2.y, R2, D, t2);
}

// ---------------------------------------------------------------------------
// torsion helper: final scalar tail for one batch
// ---------------------------------------------------------------------------
__device__ __forceinline__ float tor_tail(float dot, float m1, float m2,
                                          float V2, int ord, float ctm) {
    float c = clip1(dot * rsqrtf(fmaxf(m1 * m2, 1e-24f)));
    float c2 = 2.0f * c;
    float T1 = c;
    float T2 = fmaf(c2, T1, -1.0f);
    float T3 = fmaf(c2, T2, -T1);
    float T4 = fmaf(c2, T3, -T2);
    float T5 = fmaf(c2, T4, -T3);
    float T6 = fmaf(c2, T5, -T4);
    float Tn = (ord <= 1) ? T1 : (ord == 2) ? T2 : (ord == 3) ? T3
             : (ord == 4) ? T4 : (ord == 5) ? T5 : T6;
    return V2 * (1.0f - ctm * Tn);
}

// ---------------------------------------------------------------------------
// fused term kernel: vdw | torsion | angle | bond | inversion by block range.
// 256 threads = 64 term-groups x 4 lanes x 2 batches.
// ---------------------------------------------------------------------------
__global__ __launch_bounds__(256)
void fused_kernel(
    const float* __restrict__ coords,
    const int2* __restrict__ cidx, const float* __restrict__ cR,
    const float* __restrict__ cD,  const float* __restrict__ cT,
    int nc, int cBlocks,
    const int4* __restrict__ tidx, const float* __restrict__ tk,
    const int* __restrict__ tord,  const float* __restrict__ tcos,
    int nt, int tBlocks,
    const int* __restrict__ aidx,  const float* __restrict__ ak,
    const float* __restrict__ ac0, const float* __restrict__ ac1,
    const float* __restrict__ ac2, int na, int aBlocks,
    const int2* __restrict__ bidx, const float* __restrict__ br0,
    const float* __restrict__ bk,  int nb, int bBlocks,
    const int4* __restrict__ iidx, const float* __restrict__ ik,
    const float* __restrict__ ic0, const float* __restrict__ ic1,
    const float* __restrict__ ic2, int ni, int iBlocks,
    int natoms, float* __restrict__ out)
{
    const int blk = blockIdx.x;
    const int bp  = threadIdx.x & 3;   // batch pair (batches 2bp, 2bp+1)
    const int grp = threadIdx.x >> 2;  // term-group (0..63)
    const __half2 S8 = __float2half2_rn(0.00390625f);   // 2^-8 (exact scale)
    float e0 = 0.0f, e1 = 0.0f;

    if (blk < cBlocks) {
        // ---------------- vdW LJ (dual-chain) ----------------
        const int stride = cBlocks * 64;
        int t = blk * 64 + grp;
        for (; t + stride < nc; t += 2 * stride) {
            vdw_body(t,          bp, cidx, cR, cD, cT, coords, natoms, e0, e1);
            vdw_body(t + stride, bp, cidx, cR, cD, cT, coords, natoms, e0, e1);
        }
        if (t < nc)
            vdw_body(t, bp, cidx, cR, cD, cT, coords, natoms, e0, e1);
    } else if (blk < cBlocks + tBlocks) {
        // ---------------- torsion ----------------
        const int stride = tBlocks * 64;
        for (int t = (blk - cBlocks) * 64 + grp; t < nt; t += stride) {
            int4  q   = __ldg(&tidx[t]);
            float V2  = 0.5f * __ldg(&tk[t]);
            int   ord = __ldg(&tord[t]);
            float ctm = __ldg(&tcos[t]);
            uint4 q1 = ldco(q.x, bp);
            uint4 q2 = ldco(q.y, bp);
            uint4 q3 = ldco(q.z, bp);
            uint4 q4 = ldco(q.w, bp);
            V3h b1 = vdiff(q2, q1);
            V3h b2 = vdiff(q3, q2);
            V3h b3 = vdiff(q4, q3);
            // n1 = b1 x b2, n2 = b2 x b3 (half2, both batches); scale 2^-8
            __half2 n1x = __hmul2(cr(b1.y, b2.z, b1.z, b2.y), S8);
            __half2 n1y = __hmul2(cr(b1.z, b2.x, b1.x, b2.z), S8);
            __half2 n1z = __hmul2(cr(b1.x, b2.y, b1.y, b2.x), S8);
            __half2 n2x = __hmul2(cr(b2.y, b3.z, b2.z, b3.y), S8);
            __half2 n2y = __hmul2(cr(b2.z, b3.x, b2.x, b3.z), S8);
            __half2 n2z = __hmul2(cr(b2.x, b3.y, b2.y, b3.x), S8);
            float2 dotf = __half22float2(dot3(n1x, n1y, n1z, n2x, n2y, n2z));
            float2 m1f  = __half22float2(dot3(n1x, n1y, n1z, n1x, n1y, n1z));
            float2 m2f  = __half22float2(dot3(n2x, n2y, n2z, n2x, n2y, n2z));
            e0 += tor_tail(dotf.x, m1f.x, m2f.x, V2, ord, ctm);
            e1 += tor_tail(dotf.y, m1f.y, m2f.y, V2, ord, ctm);
        }
    } else if (blk < cBlocks + tBlocks + aBlocks) {
        // ---------------- angle ----------------
        const int base = cBlocks + tBlocks, stride = aBlocks * 64;
        for (int t = (blk - base) * 64 + grp; t < na; t += stride) {
            int i0 = __ldg(&aidx[3 * t + 0]);
            int i1 = __ldg(&aidx[3 * t + 1]);
            int i2 = __ldg(&aidx[3 * t + 2]);
            float K  = __ldg(&ak[t]);
            float a0 = __ldg(&ac0[t]);
            float a1 = __ldg(&ac1[t]);
            float a2 = __ldg(&ac2[t]);
            uint4 p1 = ldco(i0, bp);
            uint4 p2 = ldco(i1, bp);
            uint4 p3 = ldco(i2, bp);
            V3h v1 = vdiff(p1, p2);
            V3h v2 = vdiff(p3, p2);
            float2 dotf = __half22float2(dot3(v1.x, v1.y, v1.z, v2.x, v2.y, v2.z));
            float2 n1f  = __half22float2(dot3(v1.x, v1.y, v1.z, v1.x, v1.y, v1.z));
            float2 n2f  = __half22float2(dot3(v2.x, v2.y, v2.z, v2.x, v2.y, v2.z));
            #pragma unroll
            for (int s = 0; s < 2; s++) {
                float dd = s ? dotf.y : dotf.x;
                float m1 = s ? n1f.y  : n1f.x;
                float m2 = s ? n2f.y  : n2f.x;
                float ct = clip1(dd * rsqrtf(fmaxf(m1 * m2, 1e-24f)));
                float cs = ct * ct;
                float ss = fmaxf(1.0f - cs, 1e-12f);
                float ee = K * fmaf(a2, cs - ss, fmaf(a1, ct, a0));
                if (s) e1 += ee; else e0 += ee;
            }
        }
    } else if (blk < cBlocks + tBlocks + aBlocks + bBlocks) {
        // ---------------- bond ----------------
        const int base = cBlocks + tBlocks + aBlocks, stride = bBlocks * 64;
        for (int t = (blk - base) * 64 + grp; t < nb; t += stride) {
            int2  p  = __ldg(&bidx[t]);
            float r0 = __ldg(&br0[t]);
            float k2 = 0.5f * __ldg(&bk[t]);
            V3h d = vdiff(ldco(p.x, bp), ldco(p.y, bp));
            float2 d2 = __half22float2(dot3(d.x, d.y, d.z, d.x, d.y, d.z));
            float s0 = fmaxf(d2.x, 1e-24f);
            float s1 = fmaxf(d2.y, 1e-24f);
            float dd0 = s0 * rsqrtf(s0) - r0;   // sqrt - r0
            float dd1 = s1 * rsqrtf(s1) - r0;
            e0 += k2 * dd0 * dd0;
            e1 += k2 * dd1 * dd1;
        }
    } else {
        // ---------------- inversion ----------------
        const int base = cBlocks + tBlocks + aBlocks + bBlocks, stride = iBlocks * 64;
        for (int t = (blk - base) * 64 + grp; t < ni; t += stride) {
            int4  q  = __ldg(&iidx[t]);
            float K  = __ldg(&ik[t]);
            float a0 = __ldg(&ic0[t]);
            float a1 = __ldg(&ic1[t]);
            float a2 = __ldg(&ic2[t]);
            uint4 pj = ldco(q.y, bp);  // central
            V3h ri = vdiff(ldco(q.x, bp), pj);
            V3h rk = vdiff(ldco(q.z, bp), pj);
            V3h rl = vdiff(ldco(q.w, bp), pj);
            // n = ri x rk, scaled 2^-8
            __half2 nx = __hmul2(cr(ri.y, rk.z, ri.z, rk.y), S8);
            __half2 ny = __hmul2(cr(ri.z, rk.x, ri.x, rk.z), S8);
            __half2 nz = __hmul2(cr(ri.x, rk.y, ri.y, rk.x), S8);
            float2 dotf = __half22float2(dot3(nx, ny, nz, rl.x, rl.y, rl.z));
            float2 m1f  = __half22float2(dot3(nx, ny, nz, nx, ny, nz));
            float2 m2f  = __half22float2(dot3(rl.x, rl.y, rl.z, rl.x, rl.y, rl.z));
            #pragma unroll
            for (int s = 0; s < 2; s++) {
                float dd = s ? dotf.y : dotf.x;
                float m1 = s ? m1f.y  : m1f.x;
                float m2 = s ? m2f.y  : m2f.x;
                float cosY = clip1(dd * rsqrtf(fmaxf(m1 * m2, 1e-24f)));
                float s2 = fmaxf(1.0f - cosY * cosY, 1e-24f);
                float sinY = s2 * rsqrtf(s2);  // sqrt
                float ee = K * fmaf(a2, fmaf(2.0f * sinY, sinY, -1.0f), fmaf(a1, sinY, a0));
                if (s) e1 += ee; else e0 += ee;
            }
        }
    }

    reduce_out2(e0, e1, out);
}

// ---------------------------------------------------------------------------
// launch
// ---------------------------------------------------------------------------
static inline int blocks_for(int n_terms, int iters) {
    long long groups = ((long long)n_terms + 64LL * iters - 1) / (64LL * iters);
    return groups < 1 ? 1 : (int)groups;
}

extern "C" void kernel_launch(void* const* d_in, const int* in_sizes, int n_in,
                              void* d_out, int out_size) {
    const float* coords      = (const float*)d_in[0];
    const int*   bond_index  = (const int*)d_in[1];
    const float* bond_r0     = (const float*)d_in[2];
    const float* bond_k      = (const float*)d_in[3];
    const int*   angle_index = (const int*)d_in[4];
    const float* angle_k     = (const float*)d_in[5];
    const float* angle_c0    = (const float*)d_in[6];
    const float* angle_c1    = (const float*)d_in[7];
    const float* angle_c2    = (const float*)d_in[8];
    const int*   tor_index   = (const int*)d_in[9];
    const float* tor_k       = (const float*)d_in[10];
    const int*   tor_order   = (const int*)d_in[11];
    const float* tor_cos     = (const float*)d_in[12];
    const int*   inv_index   = (const int*)d_in[13];
    const float* inv_k       = (const float*)d_in[14];
    const float* inv_c0      = (const float*)d_in[15];
    const float* inv_c1      = (const float*)d_in[16];
    const float* inv_c2      = (const float*)d_in[17];
    const int*   nb_index    = (const int*)d_in[18];
    const float* vdw_min     = (const float*)d_in[19];
    const float* vdw_depth   = (const float*)d_in[20];
    const float* vdw_thr     = (const float*)d_in[21];
    float* out = (float*)d_out;

    const int NB = in_sizes[1]  / 2;
    const int NA = in_sizes[4]  / 3;
    const int NT = in_sizes[9]  / 4;
    const int NI = in_sizes[13] / 4;
    const int NC = in_sizes[18] / 2;
    const int natoms = in_sizes[0] / (3 * NBATCH);  // B fixed = 8
    const int total  = natoms * 4;

    const int T = 256;
    pack_kernel<<<(total + T - 1) / T, T>>>(coords, out, natoms);

    const int cB = blocks_for(NC, 4);
    const int tB = blocks_for(NT, 2);
    const int aB = blocks_for(NA, 2);
    const int bB = blocks_for(NB, 1);
    const int iB = blocks_for(NI, 1);
    const int grid = cB + tB + aB + bB + iB;

    fused_kernel<<<grid, T>>>(
        coords,
        (const int2*)nb_index, vdw_min, vdw_depth, vdw_thr, NC, cB,
        (const int4*)tor_index, tor_k, tor_order, tor_cos, NT, tB,
        angle_index, angle_k, angle_c0, angle_c1, angle_c2, NA, aB,
        (const int2*)bond_index, bond_r0, bond_k, NB, bB,
        (const int4*)inv_index, inv_k, inv_c0, inv_c1, inv_c2, NI, iB,
        natoms, out);
}

// round 10
// speedup vs baseline: 1.1040x; 1.1040x over previous
#include <cuda_runtime.h>
#include <cuda_bf16.h>
#include <cuda_fp16.h>

// ---------------------------------------------------------------------------
// UFF energy -> out[8]. Coords batch-major fp16 half4: g_h[atom*8+b].
// 4 lanes x 2 batches per term (uint4 coord loads = 2 batches per load).
// This round: QUAD-chain vdW (4 independent term bodies in flight) and
// dual-chain torsion, to deepen per-thread memory-level parallelism.
// fp32 math from half-diffs (half2 SIMD math regressed in R9 — same fma pipe).
// ---------------------------------------------------------------------------

#define NBATCH 8
#define MAX_ATOMS 50000

__device__ uint2 g_h[MAX_ATOMS * NBATCH];   // [atom][batch] half4 (8B)

__device__ __forceinline__ float clip1(float x) {
    return fminf(fmaxf(x, -0.999999f), 0.999999f);
}

__device__ __forceinline__ __half2 u2h(unsigned u) {
    return *reinterpret_cast<__half2*>(&u);
}

// load both batches (2*bp, 2*bp+1) of one atom: 16B
__device__ __forceinline__ uint4 ldco2(int atom, int bp) {
    const uint4* g4 = reinterpret_cast<const uint4*>(g_h);
    return __ldg(&g4[atom * 4 + bp]);
}

// d0,d1 = per-batch (a - c) differences, computed in half2 then widened
__device__ __forceinline__ void hdiff2(uint4 a, uint4 c, float3& d0, float3& d1) {
    __half2 dxy0 = __hsub2(u2h(a.x), u2h(c.x));
    __half2 dz0  = __hsub2(u2h(a.y), u2h(c.y));
    __half2 dxy1 = __hsub2(u2h(a.z), u2h(c.z));
    __half2 dz1  = __hsub2(u2h(a.w), u2h(c.w));
    float2 f0 = __half22float2(dxy0);
    float2 f1 = __half22float2(dxy1);
    d0 = make_float3(f0.x, f0.y, __low2float(dz0));
    d1 = make_float3(f1.x, f1.y, __low2float(dz1));
}

// ---------------------------------------------------------------------------
// pack coords (B,N,3) f32 -> batch-major half4; zero out[8]
// ---------------------------------------------------------------------------
__global__ void pack_kernel(const float* __restrict__ coords,
                            float* __restrict__ out, int natoms) {
    int i = blockIdx.x * blockDim.x + threadIdx.x;
    if (i < NBATCH) out[i] = 0.0f;
    if (i < natoms * NBATCH) {
        int atom = i >> 3;
        int b    = i & 7;
        size_t src = ((size_t)b * natoms + atom) * 3;
        __half2 hxy = __floats2half2_rn(coords[src], coords[src + 1]);
        __half2 hz  = __floats2half2_rn(coords[src + 2], 0.0f);
        uint2 u;
        u.x = *reinterpret_cast<unsigned*>(&hxy);
        u.y = *reinterpret_cast<unsigned*>(&hz);
        g_h[i] = u;
    }
}

// ---------------------------------------------------------------------------
// reduction: thread holds e0 (batch 2*bp) and e1 (batch 2*bp+1), bp = lane&3
// ---------------------------------------------------------------------------
__device__ __forceinline__ void reduce_out2(float e0, float e1,
                                            float* __restrict__ out) {
    #pragma unroll
    for (int off = 16; off >= 4; off >>= 1) {
        e0 += __shfl_down_sync(0xFFFFFFFFu, e0, off);
        e1 += __shfl_down_sync(0xFFFFFFFFu, e1, off);
    }
    __shared__ float s[NBATCH];
    if (threadIdx.x < NBATCH) s[threadIdx.x] = 0.0f;
    __syncthreads();
    if ((threadIdx.x & 31) < 4) {
        int bp = threadIdx.x & 3;
        atomicAdd(&s[2 * bp],     e0);
        atomicAdd(&s[2 * bp + 1], e1);
    }
    __syncthreads();
    if (threadIdx.x < NBATCH) atomicAdd(&out[threadIdx.x], s[threadIdx.x]);
}

// ---------------------------------------------------------------------------
// fp32 fallback distance^2 for near-collision vdW pairs
// ---------------------------------------------------------------------------
__device__ __forceinline__ float d2_fp32(const float* __restrict__ coords,
                                         int natoms, int b, int2 p) {
    size_t sa = ((size_t)b * natoms + p.x) * 3;
    size_t sc = ((size_t)b * natoms + p.y) * 3;
    float dx = __ldg(&coords[sa])     - __ldg(&coords[sc]);
    float dy = __ldg(&coords[sa + 1]) - __ldg(&coords[sc + 1]);
    float dz = __ldg(&coords[sa + 2]) - __ldg(&coords[sc + 2]);
    return fmaf(dx, dx, fmaf(dy, dy, dz * dz));
}

__device__ __forceinline__ float lj(float d2, float R2, float D, float t2) {
    float x2 = R2 * __fdividef(1.0f, fmaxf(d2, 1e-12f));
    float x6 = x2 * x2 * x2;
    float ep = D * fmaf(x6, x6, -2.0f * x6);
    return (d2 <= t2) ? ep : 0.0f;
}

// ---------------------------------------------------------------------------
// term bodies (each evaluates batches 2*bp and 2*bp+1)
// ---------------------------------------------------------------------------
__device__ __forceinline__ void vdw_body(
    int t, int bp, const int2* __restrict__ cidx, const float* __restrict__ cR,
    const float* __restrict__ cD, const float* __restrict__ cT,
    const float* __restrict__ coords, int natoms, float& e0, float& e1)
{
    int2  p  = __ldg(&cidx[t]);
    float R  = __ldg(&cR[t]);
    float D  = __ldg(&cD[t]);
    float t2 = __ldg(&cT[t]);
    uint4 A = ldco2(p.x, bp);
    uint4 C = ldco2(p.y, bp);
    float3 d0, d1;
    hdiff2(A, C, d0, d1);
    float d20 = fmaf(d0.x, d0.x, fmaf(d0.y, d0.y, d0.z * d0.z));
    float d21 = fmaf(d1.x, d1.x, fmaf(d1.y, d1.y, d1.z * d1.z));
    if (d20 < 4.0f) d20 = d2_fp32(coords, natoms, 2 * bp,     p);
    if (d21 < 4.0f) d21 = d2_fp32(coords, natoms, 2 * bp + 1, p);
    float R2 = R * R;
    e0 += lj(d20, R2, D, t2);
    e1 += lj(d21, R2, D, t2);
}

__device__ __forceinline__ float tor_e(float3 b1, float3 b2, float3 b3,
                                       float V2, int ord, float ctm) {
    float n1x = b1.y * b2.z - b1.z * b2.y;
    float n1y = b1.z * b2.x - b1.x * b2.z;
    float n1z = b1.x * b2.y - b1.y * b2.x;
    float n2x = b2.y * b3.z - b2.z * b3.y;
    float n2y = b2.z * b3.x - b2.x * b3.z;
    float n2z = b2.x * b3.y - b2.y * b3.x;
    float dot = fmaf(n1x, n2x, fmaf(n1y, n2y, n1z * n2z));
    float m1  = fmaf(n1x, n1x, fmaf(n1y, n1y, n1z * n1z));
    float m2  = fmaf(n2x, n2x, fmaf(n2y, n2y, n2z * n2z));
    float c   = clip1(dot * rsqrtf(fmaxf(m1 * m2, 1e-24f)));
    float c2 = 2.0f * c;
    float T1 = c;
    float T2 = fmaf(c2, T1, -1.0f);
    float T3 = fmaf(c2, T2, -T1);
    float T4 = fmaf(c2, T3, -T2);
    float T5 = fmaf(c2, T4, -T3);
    float T6 = fmaf(c2, T5, -T4);
    float Tn = (ord <= 1) ? T1 : (ord == 2) ? T2 : (ord == 3) ? T3
             : (ord == 4) ? T4 : (ord == 5) ? T5 : T6;
    return V2 * (1.0f - ctm * Tn);
}

__device__ __forceinline__ void torsion_body(
    int t, int bp, const int4* __restrict__ tidx, const float* __restrict__ tk,
    const int* __restrict__ tord, const float* __restrict__ tcos,
    float& e0, float& e1)
{
    int4  q   = __ldg(&tidx[t]);
    float V2  = 0.5f * __ldg(&tk[t]);
    int   ord = __ldg(&tord[t]);
    float ctm = __ldg(&tcos[t]);
    uint4 q1 = ldco2(q.x, bp);
    uint4 q2 = ldco2(q.y, bp);
    uint4 q3 = ldco2(q.z, bp);
    uint4 q4 = ldco2(q.w, bp);
    float3 b1a, b1b, b2a, b2b, b3a, b3b;
    hdiff2(q2, q1, b1a, b1b);
    hdiff2(q3, q2, b2a, b2b);
    hdiff2(q4, q3, b3a, b3b);
    e0 += tor_e(b1a, b2a, b3a, V2, ord, ctm);
    e1 += tor_e(b1b, b2b, b3b, V2, ord, ctm);
}

// ---------------------------------------------------------------------------
// fused term kernel: vdw | torsion | angle | bond | inversion by block range.
// 256 threads = 64 term-groups x 4 lanes x 2 batches.
// ---------------------------------------------------------------------------
__global__ __launch_bounds__(256)
void fused_kernel(
    const float* __restrict__ coords,
    const int2* __restrict__ cidx, const float* __restrict__ cR,
    const float* __restrict__ cD,  const float* __restrict__ cT,
    int nc, int cBlocks,
    const int4* __restrict__ tidx, const float* __restrict__ tk,
    const int* __restrict__ tord,  const float* __restrict__ tcos,
    int nt, int tBlocks,
    const int* __restrict__ aidx,  const float* __restrict__ ak,
    const float* __restrict__ ac0, const float* __restrict__ ac1,
    const float* __restrict__ ac2, int na, int aBlocks,
    const int2* __restrict__ bidx, const float* __restrict__ br0,
    const float* __restrict__ bk,  int nb, int bBlocks,
    const int4* __restrict__ iidx, const float* __restrict__ ik,
    const float* __restrict__ ic0, const float* __restrict__ ic1,
    const float* __restrict__ ic2, int ni, int iBlocks,
    int natoms, float* __restrict__ out)
{
    const int blk = blockIdx.x;
    const int bp  = threadIdx.x & 3;   // batch pair (batches 2bp, 2bp+1)
    const int grp = threadIdx.x >> 2;  // term-group (0..63)
    float e0 = 0.0f, e1 = 0.0f;

    if (blk < cBlocks) {
        // ---------------- vdW LJ (QUAD-chain) ----------------
        const int stride = cBlocks * 64;
        int t = blk * 64 + grp;
        for (; t + 3 * stride < nc; t += 4 * stride) {
            vdw_body(t,              bp, cidx, cR, cD, cT, coords, natoms, e0, e1);
            vdw_body(t + stride,     bp, cidx, cR, cD, cT, coords, natoms, e0, e1);
            vdw_body(t + 2 * stride, bp, cidx, cR, cD, cT, coords, natoms, e0, e1);
            vdw_body(t + 3 * stride, bp, cidx, cR, cD, cT, coords, natoms, e0, e1);
        }
        for (; t < nc; t += stride)
            vdw_body(t, bp, cidx, cR, cD, cT, coords, natoms, e0, e1);
    } else if (blk < cBlocks + tBlocks) {
        // ---------------- torsion (dual-chain) ----------------
        const int stride = tBlocks * 64;
        int t = (blk - cBlocks) * 64 + grp;
        for (; t + stride < nt; t += 2 * stride) {
            torsion_body(t,          bp, tidx, tk, tord, tcos, e0, e1);
            torsion_body(t + stride, bp, tidx, tk, tord, tcos, e0, e1);
        }
        if (t < nt)
            torsion_body(t, bp, tidx, tk, tord, tcos, e0, e1);
    } else if (blk < cBlocks + tBlocks + aBlocks) {
        // ---------------- angle ----------------
        const int base = cBlocks + tBlocks, stride = aBlocks * 64;
        for (int t = (blk - base) * 64 + grp; t < na; t += stride) {
            int i0 = __ldg(&aidx[3 * t + 0]);
            int i1 = __ldg(&aidx[3 * t + 1]);
            int i2 = __ldg(&aidx[3 * t + 2]);
            float K  = __ldg(&ak[t]);
            float a0 = __ldg(&ac0[t]);
            float a1 = __ldg(&ac1[t]);
            float a2 = __ldg(&ac2[t]);
            uint4 p1 = ldco2(i0, bp);
            uint4 p2 = ldco2(i1, bp);
            uint4 p3 = ldco2(i2, bp);
            float3 v1a, v1b, v2a, v2b;
            hdiff2(p1, p2, v1a, v1b);
            hdiff2(p3, p2, v2a, v2b);
            #pragma unroll
            for (int s = 0; s < 2; s++) {
                float3 v1 = s ? v1b : v1a;
                float3 v2 = s ? v2b : v2a;
                float dot = fmaf(v1.x, v2.x, fmaf(v1.y, v2.y, v1.z * v2.z));
                float n1  = fmaf(v1.x, v1.x, fmaf(v1.y, v1.y, v1.z * v1.z));
                float n2  = fmaf(v2.x, v2.x, fmaf(v2.y, v2.y, v2.z * v2.z));
                float ct  = clip1(dot * rsqrtf(fmaxf(n1 * n2, 1e-24f)));
                float cs  = ct * ct;
                float ss  = fmaxf(1.0f - cs, 1e-12f);
                float ee  = K * fmaf(a2, cs - ss, fmaf(a1, ct, a0));
                if (s) e1 += ee; else e0 += ee;
            }
        }
    } else if (blk < cBlocks + tBlocks + aBlocks + bBlocks) {
        // ---------------- bond ----------------
        const int base = cBlocks + tBlocks + aBlocks, stride = bBlocks * 64;
        for (int t = (blk - base) * 64 + grp; t < nb; t += stride) {
            int2  p  = __ldg(&bidx[t]);
            float r0 = __ldg(&br0[t]);
            float k2 = 0.5f * __ldg(&bk[t]);
            uint4 A = ldco2(p.x, bp);
            uint4 C = ldco2(p.y, bp);
            float3 d0, d1;
            hdiff2(A, C, d0, d1);
            float s0 = fmaxf(fmaf(d0.x, d0.x, fmaf(d0.y, d0.y, d0.z * d0.z)), 1e-24f);
            float s1 = fmaxf(fmaf(d1.x, d1.x, fmaf(d1.y, d1.y, d1.z * d1.z)), 1e-24f);
            float dd0 = s0 * rsqrtf(s0) - r0;   // sqrt(s0) - r0
            float dd1 = s1 * rsqrtf(s1) - r0;
            e0 += k2 * dd0 * dd0;
            e1 += k2 * dd1 * dd1;
        }
    } else {
        // ---------------- inversion ----------------
        const int base = cBlocks + tBlocks + aBlocks + bBlocks, stride = iBlocks * 64;
        for (int t = (blk - base) * 64 + grp; t < ni; t += stride) {
            int4  q  = __ldg(&iidx[t]);
            float K  = __ldg(&ik[t]);
            float a0 = __ldg(&ic0[t]);
            float a1 = __ldg(&ic1[t]);
            float a2 = __ldg(&ic2[t]);
            uint4 pi = ldco2(q.x, bp);
            uint4 pj = ldco2(q.y, bp);  // central
            uint4 pk = ldco2(q.z, bp);
            uint4 pl = ldco2(q.w, bp);
            float3 ia, ib, ka, kb, la, lb;
            hdiff2(pi, pj, ia, ib);
            hdiff2(pk, pj, ka, kb);
            hdiff2(pl, pj, la, lb);
            #pragma unroll
            for (int s = 0; s < 2; s++) {
                float3 vi = s ? ib : ia;
                float3 vk = s ? kb : ka;
                float3 vl = s ? lb : la;
                float nx = vi.y * vk.z - vi.z * vk.y;
                float ny = vi.z * vk.x - vi.x * vk.z;
                float nz = vi.x * vk.y - vi.y * vk.x;
                float dot = fmaf(nx, vl.x, fmaf(ny, vl.y, nz * vl.z));
                float m1  = fmaf(nx, nx, fmaf(ny, ny, nz * nz));
                float m2  = fmaf(vl.x, vl.x, fmaf(vl.y, vl.y, vl.z * vl.z));
                float cosY = clip1(dot * rsqrtf(fmaxf(m1 * m2, 1e-24f)));
                float s2 = fmaxf(1.0f - cosY * cosY, 1e-24f);
                float sinY = s2 * rsqrtf(s2);  // sqrt
                float ee = K * fmaf(a2, fmaf(2.0f * sinY, sinY, -1.0f), fmaf(a1, sinY, a0));
                if (s) e1 += ee; else e0 += ee;
            }
        }
    }

    reduce_out2(e0, e1, out);
}

// ---------------------------------------------------------------------------
// launch
// ---------------------------------------------------------------------------
static inline int blocks_for(int n_terms, int iters) {
    long long groups = ((long long)n_terms + 64LL * iters - 1) / (64LL * iters);
    return groups < 1 ? 1 : (int)groups;
}

extern "C" void kernel_launch(void* const* d_in, const int* in_sizes, int n_in,
                              void* d_out, int out_size) {
    const float* coords      = (const float*)d_in[0];
    const int*   bond_index  = (const int*)d_in[1];
    const float* bond_r0     = (const float*)d_in[2];
    const float* bond_k      = (const float*)d_in[3];
    const int*   angle_index = (const int*)d_in[4];
    const float* angle_k     = (const float*)d_in[5];
    const float* angle_c0    = (const float*)d_in[6];
    const float* angle_c1    = (const float*)d_in[7];
    const float* angle_c2    = (const float*)d_in[8];
    const int*   tor_index   = (const int*)d_in[9];
    const float* tor_k       = (const float*)d_in[10];
    const int*   tor_order   = (const int*)d_in[11];
    const float* tor_cos     = (const float*)d_in[12];
    const int*   inv_index   = (const int*)d_in[13];
    const float* inv_k       = (const float*)d_in[14];
    const float* inv_c0      = (const float*)d_in[15];
    const float* inv_c1      = (const float*)d_in[16];
    const float* inv_c2      = (const float*)d_in[17];
    const int*   nb_index    = (const int*)d_in[18];
    const float* vdw_min     = (const float*)d_in[19];
    const float* vdw_depth   = (const float*)d_in[20];
    const float* vdw_thr     = (const float*)d_in[21];
    float* out = (float*)d_out;

    const int NB = in_sizes[1]  / 2;
    const int NA = in_sizes[4]  / 3;
    const int NT = in_sizes[9]  / 4;
    const int NI = in_sizes[13] / 4;
    const int NC = in_sizes[18] / 2;
    const int natoms = in_sizes[0] / (3 * NBATCH);  // B fixed = 8
    const int total  = NBATCH * natoms;

    const int T = 256;
    pack_kernel<<<(total + T - 1) / T, T>>>(coords, out, natoms);

    const int cB = blocks_for(NC, 4);
    const int tB = blocks_for(NT, 2);
    const int aB = blocks_for(NA, 2);
    const int bB = blocks_for(NB, 1);
    const int iB = blocks_for(NI, 1);
    const int grid = cB + tB + aB + bB + iB;

    fused_kernel<<<grid, T>>>(
        coords,
        (const int2*)nb_index, vdw_min, vdw_depth, vdw_thr, NC, cB,
        (const int4*)tor_index, tor_k, tor_order, tor_cos, NT, tB,
        angle_index, angle_k, angle_c0, angle_c1, angle_c2, NA, aB,
        (const int2*)bond_index, bond_r0, bond_k, NB, bB,
        (const int4*)inv_index, inv_k, inv_c0, inv_c1, inv_c2, NI, iB,
        natoms, out);
}